// round 1
// baseline (speedup 1.0000x reference)
#include <cuda_runtime.h>

#define NN 100000
#define FD 128
#define BB 50
#define PP 2000
#define CC 10
#define KINV (1.0f/30.0f)

// Scratch (static device globals — no allocation at launch time).
static __device__ float g_tmp[NN*FD];        // h @ W (transformed features, gather source)
static __device__ float g_h1[NN*FD];         // layer-1 pre-relu output
static __device__ float g_h2[NN*FD];         // layer-2 pre-relu output
static __device__ float g_inv[NN];           // deg -> rsqrt(deg)
static __device__ float g_part[BB*8*FD];     // pooling partials

// ---------------- degree / normalization ----------------

__global__ void k_deg_init() {
    int i = blockIdx.x*blockDim.x + threadIdx.x;
    if (i < NN) g_inv[i] = 1.0f;              // self-loop: deg = in_deg + 1
}

__global__ void k_deg_acc(const int* __restrict__ ei, int E) {
    int e = blockIdx.x*blockDim.x + threadIdx.x;
    if (e < E) atomicAdd(&g_inv[ei[E + e]], 1.0f);   // dst row of edge_index
}

__global__ void k_deg_fin() {
    int i = blockIdx.x*blockDim.x + threadIdx.x;
    if (i < NN) g_inv[i] = rsqrtf(g_inv[i]);
}

// ---------------- fused SGEMM (+ self-loop/bias epilogue) ----------------
// C = act(A) @ W  (128x128 W). Writes Tout = C and Hout = C*inv^2 + bias.
// LAYER==1: A = X (no relu), Hout = g_h1. LAYER==2: A = relu(g_h1), Hout = g_h2.

template<int LAYER>
__global__ void __launch_bounds__(256)
k_gemm(const float* __restrict__ X, const float* __restrict__ W,
       const float* __restrict__ bias) {
    const float* A  = (LAYER == 1) ? X : (const float*)g_h1;
    float* Tout     = g_tmp;
    float* Hout     = (LAYER == 1) ? g_h1 : g_h2;

    __shared__ float As[32][129];   // transposed A chunk: As[kk][row]
    __shared__ float Ws[32][128];   // W chunk: Ws[kk][col]

    const int tid  = threadIdx.x;          // 256 threads
    const int row0 = blockIdx.x * 128;
    const int rq   = tid >> 4;              // 0..15 -> 8 rows each
    const int cq   = tid & 15;              // 0..15 -> 8 cols each

    float acc[8][8];
    #pragma unroll
    for (int i = 0; i < 8; i++)
        #pragma unroll
        for (int j = 0; j < 8; j++) acc[i][j] = 0.f;

    for (int k0 = 0; k0 < FD; k0 += 32) {
        // Load A[row0..+127][k0..+31] transposed into As (conflict-free stores)
        #pragma unroll
        for (int i = 0; i < 4; i++) {
            int s  = tid + i*256;       // 0..1023 float4 slots
            int r  = s >> 3;            // 0..127
            int kv = s & 7;             // float4 within row
            int grow = row0 + r;
            float4 v = make_float4(0.f, 0.f, 0.f, 0.f);
            if (grow < NN)
                v = *reinterpret_cast<const float4*>(A + (size_t)grow*FD + k0 + kv*4);
            if (LAYER == 2) {
                v.x = fmaxf(v.x, 0.f); v.y = fmaxf(v.y, 0.f);
                v.z = fmaxf(v.z, 0.f); v.w = fmaxf(v.w, 0.f);
            }
            As[kv*4+0][r] = v.x; As[kv*4+1][r] = v.y;
            As[kv*4+2][r] = v.z; As[kv*4+3][r] = v.w;
        }
        // Load W[k0..+31][0..127]
        #pragma unroll
        for (int i = 0; i < 4; i++) {
            int s  = tid + i*256;
            int kk = s >> 5;
            int jv = s & 31;
            *reinterpret_cast<float4*>(&Ws[kk][jv*4]) =
                *reinterpret_cast<const float4*>(W + (size_t)(k0+kk)*FD + jv*4);
        }
        __syncthreads();

        #pragma unroll
        for (int kk = 0; kk < 32; kk++) {
            float a[8], w[8];
            #pragma unroll
            for (int i = 0; i < 8; i++) a[i] = As[kk][rq*8 + i];
            *reinterpret_cast<float4*>(&w[0]) =
                *reinterpret_cast<const float4*>(&Ws[kk][cq*8]);
            *reinterpret_cast<float4*>(&w[4]) =
                *reinterpret_cast<const float4*>(&Ws[kk][cq*8 + 4]);
            #pragma unroll
            for (int i = 0; i < 8; i++)
                #pragma unroll
                for (int j = 0; j < 8; j++)
                    acc[i][j] = fmaf(a[i], w[j], acc[i][j]);
        }
        __syncthreads();
    }

    // Epilogue: tmp = C ; h = C*inv^2 + b
    #pragma unroll
    for (int i = 0; i < 8; i++) {
        int grow = row0 + rq*8 + i;
        if (grow < NN) {
            float iv   = g_inv[grow];
            float self = iv * iv;
            #pragma unroll
            for (int j = 0; j < 8; j += 4) {
                int col = cq*8 + j;
                float4 t = make_float4(acc[i][j], acc[i][j+1], acc[i][j+2], acc[i][j+3]);
                *reinterpret_cast<float4*>(Tout + (size_t)grow*FD + col) = t;
                float4 h;
                h.x = fmaf(t.x, self, bias[col+0]);
                h.y = fmaf(t.y, self, bias[col+1]);
                h.z = fmaf(t.z, self, bias[col+2]);
                h.w = fmaf(t.w, self, bias[col+3]);
                *reinterpret_cast<float4*>(Hout + (size_t)grow*FD + col) = h;
            }
        }
    }
}

// ---------------- edge propagation: one warp per edge ----------------
// H[dst] += tmp[src] * inv[src]*inv[dst], 128 floats via red.global.add.v4.f32

template<int LAYER>
__global__ void k_scatter(const int* __restrict__ ei, int E) {
    int e = blockIdx.x*8 + (threadIdx.x >> 5);
    if (e >= E) return;
    float* H = (LAYER == 1) ? g_h1 : g_h2;

    int lane = threadIdx.x & 31;
    int src  = __ldg(ei + e);
    int dst  = __ldg(ei + E + e);
    float c  = g_inv[src] * g_inv[dst];

    float4 v = *reinterpret_cast<const float4*>(g_tmp + (size_t)src*FD + lane*4);
    float* p = H + (size_t)dst*FD + lane*4;
    asm volatile("red.global.add.v4.f32 [%0], {%1, %2, %3, %4};"
                 :: "l"(p), "f"(v.x*c), "f"(v.y*c), "f"(v.z*c), "f"(v.w*c)
                 : "memory");
}

// ---------------- pooling: mean over K clusters == (1/K) * sum_n relu(h2) ----------------

__global__ void k_pool() {
    int b = blockIdx.x >> 3;
    int q = blockIdx.x & 7;
    int d = threadIdx.x;                          // 128 threads
    const float* base = g_h2 + ((size_t)(b*PP + q*(PP/8)))*FD + d;
    float s = 0.f;
    #pragma unroll 4
    for (int n = 0; n < PP/8; n++) s += fmaxf(base[(size_t)n*FD], 0.f);
    g_part[blockIdx.x*FD + d] = s;
}

__global__ void k_final(const float* __restrict__ Wl, const float* __restrict__ bl,
                        float* __restrict__ out) {
    int t = threadIdx.x;
    if (t >= BB*CC) return;
    int b = t / CC, c = t % CC;
    float s = 0.f;
    for (int d = 0; d < FD; d++) {
        float p = 0.f;
        #pragma unroll
        for (int q = 0; q < 8; q++) p += g_part[(b*8 + q)*FD + d];
        s = fmaf(p, Wl[d*CC + c], s);
    }
    out[t] = fmaf(s, KINV, bl[c]);
}

// ---------------- launch ----------------

extern "C" void kernel_launch(void* const* d_in, const int* in_sizes, int n_in,
                              void* d_out, int out_size) {
    const float* x  = (const float*)d_in[0];
    const int*   ei = (const int*)  d_in[1];
    // d_in[2] = batch (implied by block structure, unused)
    const float* W1 = (const float*)d_in[3];
    const float* b1 = (const float*)d_in[4];
    const float* W2 = (const float*)d_in[5];
    const float* b2 = (const float*)d_in[6];
    // d_in[7]=Wa, d_in[8]=ba — mathematically dead (softmax rows sum to 1)
    const float* Wl = (const float*)d_in[9];
    const float* bl = (const float*)d_in[10];
    float* out = (float*)d_out;

    const int E = in_sizes[1] / 2;

    // degree -> rsqrt
    k_deg_init<<<(NN + 255)/256, 256>>>();
    k_deg_acc <<<(E  + 255)/256, 256>>>(ei, E);
    k_deg_fin <<<(NN + 255)/256, 256>>>();

    const int gemm_grid = (NN + 127)/128;
    const int scat_grid = (E + 7)/8;

    // Layer 1: tmp = x@W1 ; h1 = tmp*inv^2 + b1 ; h1 += scatter
    k_gemm<1><<<gemm_grid, 256>>>(x, W1, b1);
    k_scatter<1><<<scat_grid, 256>>>(ei, E);

    // Layer 2: tmp = relu(h1)@W2 ; h2 = tmp*inv^2 + b2 ; h2 += scatter
    k_gemm<2><<<gemm_grid, 256>>>(x, W2, b2);
    k_scatter<2><<<scat_grid, 256>>>(ei, E);

    // Pool relu(h2) per graph, then tiny final GEMM
    k_pool <<<BB*8, FD>>>();
    k_final<<<1, 512>>>(Wl, bl, out);
}

// round 3
// speedup vs baseline: 1.7550x; 1.7550x over previous
#include <cuda_runtime.h>

#define NN 100000
#define EE 1600000
#define FD 128
#define BB 50
#define PP 2000
#define CC 10
#define KINV (1.0f/30.0f)
#define NBLK ((NN + 255) / 256)   // 391

// Scratch (static device globals — no allocation at launch time).
static __device__ float g_tmp[NN*FD];        // (A@W) * inv[row]  (gather source)
static __device__ float g_h1[NN*FD];         // relu(layer-1 output)
static __device__ float g_h2[NN*FD];         // relu(layer-2 output)
static __device__ float g_inv[NN];           // rsqrt(deg+1)
static __device__ float g_part[BB*8*FD];     // pooling partials
static __device__ int   g_cnt[NN];           // histogram (= degree)
static __device__ int   g_cur[NN];           // fill cursors
static __device__ int   g_off[NN];           // CSR row offsets (exclusive scan)
static __device__ int   g_src[EE];           // CSR src indices (grouped by dst)
static __device__ int   g_blksum[NBLK];      // per-block scan sums
static __device__ int   g_blkoff[NBLK];      // scanned block offsets

// ---------------- CSR-by-dst construction ----------------

__global__ void k_zero() {
    int i = blockIdx.x*blockDim.x + threadIdx.x;
    if (i < NN) { g_cnt[i] = 0; g_cur[i] = 0; }
}

__global__ void k_hist(const int* __restrict__ ei, int E) {
    int e = blockIdx.x*blockDim.x + threadIdx.x;
    if (e < E) atomicAdd(&g_cnt[ei[E + e]], 1);
}

// Per-block inclusive scan of counts; writes local exclusive offsets,
// block totals, and inv = rsqrt(deg+1).
__global__ void k_scan_block() {
    __shared__ int sh[256];
    int t = threadIdx.x;
    int i = blockIdx.x*256 + t;
    int v = (i < NN) ? g_cnt[i] : 0;
    sh[t] = v;
    __syncthreads();
    #pragma unroll
    for (int d = 1; d < 256; d <<= 1) {
        int x = (t >= d) ? sh[t-d] : 0;
        __syncthreads();
        sh[t] += x;
        __syncthreads();
    }
    if (i < NN) {
        g_off[i] = sh[t] - v;                 // local exclusive
        g_inv[i] = rsqrtf((float)v + 1.0f);
    }
    if (t == 255) g_blksum[blockIdx.x] = sh[255];
}

__global__ void k_scan_top() {
    __shared__ int sh[512];
    int t = threadIdx.x;
    int v = (t < NBLK) ? g_blksum[t] : 0;
    sh[t] = v;
    __syncthreads();
    #pragma unroll
    for (int d = 1; d < 512; d <<= 1) {
        int x = (t >= d) ? sh[t-d] : 0;
        __syncthreads();
        sh[t] += x;
        __syncthreads();
    }
    if (t < NBLK) g_blkoff[t] = sh[t] - v;    // exclusive
}

__global__ void k_scan_add() {
    int i = blockIdx.x*256 + threadIdx.x;
    if (i < NN) g_off[i] += g_blkoff[blockIdx.x];
}

__global__ void k_fill(const int* __restrict__ ei, int E) {
    int e = blockIdx.x*blockDim.x + threadIdx.x;
    if (e < E) {
        int s = ei[e];
        int d = ei[E + e];
        int pos = g_off[d] + atomicAdd(&g_cur[d], 1);
        g_src[pos] = s;
    }
}

// ---------------- fused SGEMM: tmp' = (A @ W) * inv[row] ----------------
// LAYER==1: A = X (kernel arg). LAYER==2: A = g_h1 (resolved ON DEVICE —
// passing a __device__ symbol from host code was the round-2 bug).

template<int LAYER>
__global__ void __launch_bounds__(256)
k_gemm(const float* __restrict__ X, const float* __restrict__ W) {
    const float* A = (LAYER == 1) ? X : (const float*)g_h1;

    __shared__ float As[32][129];   // transposed A chunk: As[kk][row]
    __shared__ float Ws[32][128];   // W chunk: Ws[kk][col]

    const int tid  = threadIdx.x;
    const int row0 = blockIdx.x * 128;
    const int rq   = tid >> 4;
    const int cq   = tid & 15;

    float acc[8][8];
    #pragma unroll
    for (int i = 0; i < 8; i++)
        #pragma unroll
        for (int j = 0; j < 8; j++) acc[i][j] = 0.f;

    for (int k0 = 0; k0 < FD; k0 += 32) {
        #pragma unroll
        for (int i = 0; i < 4; i++) {
            int s  = tid + i*256;
            int r  = s >> 3;
            int kv = s & 7;
            int grow = row0 + r;
            float4 v = make_float4(0.f, 0.f, 0.f, 0.f);
            if (grow < NN)
                v = *reinterpret_cast<const float4*>(A + (size_t)grow*FD + k0 + kv*4);
            As[kv*4+0][r] = v.x; As[kv*4+1][r] = v.y;
            As[kv*4+2][r] = v.z; As[kv*4+3][r] = v.w;
        }
        #pragma unroll
        for (int i = 0; i < 4; i++) {
            int s  = tid + i*256;
            int kk = s >> 5;
            int jv = s & 31;
            *reinterpret_cast<float4*>(&Ws[kk][jv*4]) =
                *reinterpret_cast<const float4*>(W + (size_t)(k0+kk)*FD + jv*4);
        }
        __syncthreads();

        #pragma unroll
        for (int kk = 0; kk < 32; kk++) {
            float a[8], w[8];
            #pragma unroll
            for (int i = 0; i < 8; i++) a[i] = As[kk][rq*8 + i];
            *reinterpret_cast<float4*>(&w[0]) =
                *reinterpret_cast<const float4*>(&Ws[kk][cq*8]);
            *reinterpret_cast<float4*>(&w[4]) =
                *reinterpret_cast<const float4*>(&Ws[kk][cq*8 + 4]);
            #pragma unroll
            for (int i = 0; i < 8; i++)
                #pragma unroll
                for (int j = 0; j < 8; j++)
                    acc[i][j] = fmaf(a[i], w[j], acc[i][j]);
        }
        __syncthreads();
    }

    #pragma unroll
    for (int i = 0; i < 8; i++) {
        int grow = row0 + rq*8 + i;
        if (grow < NN) {
            float iv = g_inv[grow];
            #pragma unroll
            for (int j = 0; j < 8; j += 4) {
                int col = cq*8 + j;
                float4 t = make_float4(acc[i][j]*iv, acc[i][j+1]*iv,
                                       acc[i][j+2]*iv, acc[i][j+3]*iv);
                *reinterpret_cast<float4*>(g_tmp + (size_t)grow*FD + col) = t;
            }
        }
    }
}

// ---------------- CSR gather: one warp per dst node ----------------
// H[dst] = relu( inv[dst] * (tmp'[dst] + sum_{src in csr[dst]} tmp'[src]) + b )

template<int LAYER>
__global__ void __launch_bounds__(256)
k_gather(const float* __restrict__ bias) {
    int node = blockIdx.x*8 + (threadIdx.x >> 5);
    if (node >= NN) return;
    float* H = (LAYER == 1) ? g_h1 : g_h2;

    const int lane  = threadIdx.x & 31;
    const int start = g_off[node];
    const int deg   = g_cnt[node];

    // self term
    float4 acc0 = *reinterpret_cast<const float4*>(g_tmp + (size_t)node*FD + lane*4);
    float4 acc1 = make_float4(0.f, 0.f, 0.f, 0.f);

    for (int base = 0; base < deg; base += 32) {
        int n = deg - base; if (n > 32) n = 32;
        int s = (base + lane < deg) ? g_src[start + base + lane] : 0;
        int j = 0;
        for (; j + 1 < n; j += 2) {
            int s0 = __shfl_sync(0xffffffff, s, j);
            int s1 = __shfl_sync(0xffffffff, s, j+1);
            float4 v0 = *reinterpret_cast<const float4*>(g_tmp + (size_t)s0*FD + lane*4);
            float4 v1 = *reinterpret_cast<const float4*>(g_tmp + (size_t)s1*FD + lane*4);
            acc0.x += v0.x; acc0.y += v0.y; acc0.z += v0.z; acc0.w += v0.w;
            acc1.x += v1.x; acc1.y += v1.y; acc1.z += v1.z; acc1.w += v1.w;
        }
        if (j < n) {
            int s0 = __shfl_sync(0xffffffff, s, j);
            float4 v0 = *reinterpret_cast<const float4*>(g_tmp + (size_t)s0*FD + lane*4);
            acc0.x += v0.x; acc0.y += v0.y; acc0.z += v0.z; acc0.w += v0.w;
        }
    }

    float invd = g_inv[node];
    float4 b4 = *reinterpret_cast<const float4*>(bias + lane*4);
    float4 h;
    h.x = fmaxf(fmaf(acc0.x + acc1.x, invd, b4.x), 0.f);
    h.y = fmaxf(fmaf(acc0.y + acc1.y, invd, b4.y), 0.f);
    h.z = fmaxf(fmaf(acc0.z + acc1.z, invd, b4.z), 0.f);
    h.w = fmaxf(fmaf(acc0.w + acc1.w, invd, b4.w), 0.f);
    *reinterpret_cast<float4*>(H + (size_t)node*FD + lane*4) = h;
}

// ---------------- pooling: out[b] = (1/K) * sum_n relu(h2[n]) ----------------

__global__ void k_pool() {
    int b = blockIdx.x >> 3;
    int q = blockIdx.x & 7;
    int d = threadIdx.x;
    const float* base = g_h2 + ((size_t)(b*PP + q*(PP/8)))*FD + d;
    float s = 0.f;
    #pragma unroll 4
    for (int n = 0; n < PP/8; n++) s += base[(size_t)n*FD];   // already relu'd
    g_part[blockIdx.x*FD + d] = s;
}

__global__ void k_final(const float* __restrict__ Wl, const float* __restrict__ bl,
                        float* __restrict__ out) {
    int t = threadIdx.x;
    if (t >= BB*CC) return;
    int b = t / CC, c = t % CC;
    float s = 0.f;
    for (int d = 0; d < FD; d++) {
        float p = 0.f;
        #pragma unroll
        for (int q = 0; q < 8; q++) p += g_part[(b*8 + q)*FD + d];
        s = fmaf(p, Wl[d*CC + c], s);
    }
    out[t] = fmaf(s, KINV, bl[c]);
}

// ---------------- launch ----------------

extern "C" void kernel_launch(void* const* d_in, const int* in_sizes, int n_in,
                              void* d_out, int out_size) {
    const float* x  = (const float*)d_in[0];
    const int*   ei = (const int*)  d_in[1];
    const float* W1 = (const float*)d_in[3];
    const float* b1 = (const float*)d_in[4];
    const float* W2 = (const float*)d_in[5];
    const float* b2 = (const float*)d_in[6];
    // d_in[7]=Wa, d_in[8]=ba dead (softmax rows sum to 1); d_in[2]=batch implied
    const float* Wl = (const float*)d_in[9];
    const float* bl = (const float*)d_in[10];
    float* out = (float*)d_out;

    const int E = in_sizes[1] / 2;

    // CSR-by-dst build (also produces degrees -> g_inv)
    k_zero      <<<NBLK, 256>>>();
    k_hist      <<<(E + 511)/512, 512>>>(ei, E);
    k_scan_block<<<NBLK, 256>>>();
    k_scan_top  <<<1, 512>>>();
    k_scan_add  <<<NBLK, 256>>>();
    k_fill      <<<(E + 511)/512, 512>>>(ei, E);

    const int gemm_grid   = (NN + 127)/128;
    const int gather_grid = (NN + 7)/8;

    // Layer 1: tmp' = (x@W1)*inv ; h1 = relu(gather + b1)
    k_gemm<1>  <<<gemm_grid, 256>>>(x, W1);
    k_gather<1><<<gather_grid, 256>>>(b1);

    // Layer 2: tmp' = (h1@W2)*inv ; h2 = relu(gather + b2)
    k_gemm<2>  <<<gemm_grid, 256>>>(x /*unused*/, W2);
    k_gather<2><<<gather_grid, 256>>>(b2);

    // Pool + final tiny GEMM
    k_pool <<<BB*8, FD>>>();
    k_final<<<1, 512>>>(Wl, bl, out);
}